// round 1
// baseline (speedup 1.0000x reference)
#include <cuda_runtime.h>
#include <cuda_bf16.h>
#include <cstdint>

// ---------------------------------------------------------------------------
// DualCausalMambaBlock: B=2, L=2048, D_MODEL=1024, D_INNER=2048, N=16,
// D_CONV=4, DT_RANK=64.  M = B*L = 4096 rows.
// Pipeline:
//   1) xz = u @ W_in^T                      [4096 x 4096], K=1024
//   2) x  = silu(causal_conv(xz[:, :2048])) [4096 x 2048]
//   3) xp = x @ W_x^T                       [4096 x 96],   K=2048
//   4) dt = softplus(xp[:, :64] @ W_dt^T + b_dt)  [4096 x 2048], K=64
//   5) selective scan over L (fused +D*x and *silu(z))  -> y [4096 x 2048]
//   6) out = y @ W_out^T                    [4096 x 1024], K=2048
// ---------------------------------------------------------------------------

#define B_SZ     2
#define SEQ_L    2048
#define D_MODEL  1024
#define D_INNER  2048
#define D_STATE  16
#define D_CONV   4
#define DT_RANK  64
#define M_ROWS   (B_SZ * SEQ_L)          // 4096
#define XP_COLS  (DT_RANK + 2 * D_STATE) // 96

// Scratch (static device globals: allocation-free, allowed by harness rules)
__device__ float g_xz[(size_t)M_ROWS * (2 * D_INNER)]; // 64 MB
__device__ float g_x [(size_t)M_ROWS * D_INNER];       // 32 MB
__device__ float g_xp[(size_t)M_ROWS * XP_COLS];       // 1.5 MB
__device__ float g_dt[(size_t)M_ROWS * D_INNER];       // 32 MB
__device__ float g_y [(size_t)M_ROWS * D_INNER];       // 32 MB

// ---------------------------------------------------------------------------
// Generic tiled fp32 GEMM:  C[M,N] = A[M,K] @ B[N,K]^T  (both K-major)
// ACT: 0 = none, 1 = softplus(x + bias[col])
// BM=BN=128, BK=8, 8x8 per thread, 256 threads.
// ---------------------------------------------------------------------------
template<int ACT>
__global__ __launch_bounds__(256)
void gemm_abt(const float* __restrict__ A, int lda,
              const float* __restrict__ B, int ldb,
              float* __restrict__ C, int ldc,
              int M, int N, int K,
              const float* __restrict__ bias)
{
    constexpr int BM = 128, BN = 128, BK = 8, TM = 8, TN = 8;
    __shared__ float As[BK][BM];
    __shared__ float Bs[BK][BN];

    const int tid  = threadIdx.x;
    const int bm0  = blockIdx.y * BM;
    const int bn0  = blockIdx.x * BN;
    const int tcol = (tid % (BN / TN)) * TN;  // 0..120 step 8
    const int trow = (tid / (BN / TN)) * TM;

    // loader decomposition: one float4 per thread per tile
    const int l_r = tid >> 1;            // 0..127
    const int l_c = (tid & 1) * 4;       // 0 or 4

    float acc[TM][TN];
#pragma unroll
    for (int i = 0; i < TM; ++i)
#pragma unroll
        for (int j = 0; j < TN; ++j) acc[i][j] = 0.f;

    for (int k0 = 0; k0 < K; k0 += BK) {
        // load A tile (transposed into As[k][m])
        {
            float4 v = make_float4(0.f, 0.f, 0.f, 0.f);
            int gr = bm0 + l_r;
            if (gr < M)
                v = *reinterpret_cast<const float4*>(A + (size_t)gr * lda + k0 + l_c);
            As[l_c + 0][l_r] = v.x;
            As[l_c + 1][l_r] = v.y;
            As[l_c + 2][l_r] = v.z;
            As[l_c + 3][l_r] = v.w;
        }
        // load B tile (transposed into Bs[k][n])
        {
            float4 v = make_float4(0.f, 0.f, 0.f, 0.f);
            int gr = bn0 + l_r;
            if (gr < N)
                v = *reinterpret_cast<const float4*>(B + (size_t)gr * ldb + k0 + l_c);
            Bs[l_c + 0][l_r] = v.x;
            Bs[l_c + 1][l_r] = v.y;
            Bs[l_c + 2][l_r] = v.z;
            Bs[l_c + 3][l_r] = v.w;
        }
        __syncthreads();

#pragma unroll
        for (int k = 0; k < BK; ++k) {
            float ar[TM], br[TN];
            *reinterpret_cast<float4*>(&ar[0]) = *reinterpret_cast<const float4*>(&As[k][trow]);
            *reinterpret_cast<float4*>(&ar[4]) = *reinterpret_cast<const float4*>(&As[k][trow + 4]);
            *reinterpret_cast<float4*>(&br[0]) = *reinterpret_cast<const float4*>(&Bs[k][tcol]);
            *reinterpret_cast<float4*>(&br[4]) = *reinterpret_cast<const float4*>(&Bs[k][tcol + 4]);
#pragma unroll
            for (int i = 0; i < TM; ++i)
#pragma unroll
                for (int j = 0; j < TN; ++j)
                    acc[i][j] = fmaf(ar[i], br[j], acc[i][j]);
        }
        __syncthreads();
    }

    // epilogue
#pragma unroll
    for (int i = 0; i < TM; ++i) {
        int row = bm0 + trow + i;
        if (row >= M) continue;
#pragma unroll
        for (int j = 0; j < TN; ++j) {
            int col = bn0 + tcol + j;
            if (col >= N) continue;
            float v = acc[i][j];
            if (ACT == 1) {
                v += bias[col];
                // softplus, numerically safe
                v = (v > 20.f) ? v : log1pf(__expf(v));
            }
            C[(size_t)row * ldc + col] = v;
        }
    }
}

// ---------------------------------------------------------------------------
// Causal depthwise conv (K=4) + SiLU.  x_in = xz[:, :D_INNER] (row stride 4096)
// ---------------------------------------------------------------------------
__global__ __launch_bounds__(256)
void conv_silu_kernel(const float* __restrict__ xz,
                      const float* __restrict__ cw,
                      const float* __restrict__ cb,
                      float* __restrict__ x)
{
    int idx = blockIdx.x * blockDim.x + threadIdx.x;    // over B*L*D_INNER
    if (idx >= B_SZ * SEQ_L * D_INNER) return;
    int d = idx & (D_INNER - 1);
    int l = (idx >> 11) & (SEQ_L - 1);
    int b = idx >> 22;

    float acc = cb[d];
#pragma unroll
    for (int k = 0; k < D_CONV; ++k) {
        int ls = l - (D_CONV - 1) + k;
        if (ls >= 0)
            acc = fmaf(xz[((size_t)(b * SEQ_L + ls)) * (2 * D_INNER) + d],
                       cw[d * D_CONV + k], acc);
    }
    // silu
    float s = 1.f / (1.f + __expf(-acc));
    x[idx] = acc * s;
}

// ---------------------------------------------------------------------------
// Selective scan. Half-warp per channel: lanes [0..15] -> channel 2*gw,
// lanes [16..31] -> channel 2*gw+1. Lane n holds state h[n]. Fused with
// y = (scan + D*x) * silu(z), written to g_y.
// ---------------------------------------------------------------------------
__global__ __launch_bounds__(256)
void scan_kernel(const float* __restrict__ dt,
                 const float* __restrict__ xv,
                 const float* __restrict__ xp,
                 const float* __restrict__ xz,   // for z = xz[:, D_INNER:]
                 const float* __restrict__ A_log,
                 const float* __restrict__ Dp,
                 float* __restrict__ y)
{
    int gw   = (blockIdx.x * blockDim.x + threadIdx.x) >> 5; // global warp id
    int lane = threadIdx.x & 31;
    int sub  = lane >> 4;        // which half-warp
    int n    = lane & 15;        // state index

    int ch = gw * 2 + sub;       // 0 .. B*D_INNER-1
    if (ch >= B_SZ * D_INNER) return;
    int b = ch / D_INNER;
    int d = ch % D_INNER;

    const float Aval = -__expf(A_log[d * D_STATE + n]);
    const float Dv   = Dp[d];

    float h = 0.f;
    const int base_row = b * SEQ_L;

    for (int t = 0; t < SEQ_L; ++t) {
        int row = base_row + t;
        float dtv = dt[(size_t)row * D_INNER + d];
        float xt  = xv[(size_t)row * D_INNER + d];
        float zt  = xz[(size_t)row * (2 * D_INNER) + D_INNER + d];
        const float* xpr = xp + (size_t)row * XP_COLS;
        float Bv = xpr[DT_RANK + n];
        float Cv = xpr[DT_RANK + D_STATE + n];

        float a = __expf(dtv * Aval);
        h = fmaf(a, h, (dtv * xt) * Bv);

        float p = h * Cv;
        p += __shfl_xor_sync(0xffffffffu, p, 8);
        p += __shfl_xor_sync(0xffffffffu, p, 4);
        p += __shfl_xor_sync(0xffffffffu, p, 2);
        p += __shfl_xor_sync(0xffffffffu, p, 1);

        if (n == 0) {
            float yv = fmaf(Dv, xt, p);
            float sz = zt / (1.f + __expf(-zt));
            y[(size_t)row * D_INNER + d] = yv * sz;
        }
    }
}

// ---------------------------------------------------------------------------
extern "C" void kernel_launch(void* const* d_in, const int* in_sizes, int n_in,
                              void* d_out, int out_size)
{
    const float* u      = (const float*)d_in[0];
    const float* W_in   = (const float*)d_in[1];
    const float* W_out  = (const float*)d_in[2];
    const float* conv_w = (const float*)d_in[3];
    const float* conv_b = (const float*)d_in[4];
    const float* W_x    = (const float*)d_in[5];
    const float* W_dt   = (const float*)d_in[6];
    const float* b_dt   = (const float*)d_in[7];
    const float* A_log  = (const float*)d_in[8];
    const float* D_par  = (const float*)d_in[9];
    float* out = (float*)d_out;

    float *xz, *x, *xp, *dtp, *y;
    cudaGetSymbolAddress((void**)&xz,  g_xz);
    cudaGetSymbolAddress((void**)&x,   g_x);
    cudaGetSymbolAddress((void**)&xp,  g_xp);
    cudaGetSymbolAddress((void**)&dtp, g_dt);
    cudaGetSymbolAddress((void**)&y,   g_y);

    // 1) xz = u @ W_in^T   [4096 x 4096], K=1024
    gemm_abt<0><<<dim3((2 * D_INNER) / 128, M_ROWS / 128), 256>>>(
        u, D_MODEL, W_in, D_MODEL, xz, 2 * D_INNER,
        M_ROWS, 2 * D_INNER, D_MODEL, nullptr);

    // 2) causal conv + silu
    {
        int total = B_SZ * SEQ_L * D_INNER;
        conv_silu_kernel<<<(total + 255) / 256, 256>>>(xz, conv_w, conv_b, x);
    }

    // 3) xp = x @ W_x^T   [4096 x 96], K=2048
    gemm_abt<0><<<dim3(1, M_ROWS / 128), 256>>>(
        x, D_INNER, W_x, D_INNER, xp, XP_COLS,
        M_ROWS, XP_COLS, D_INNER, nullptr);

    // 4) dt = softplus(xp[:, :64] @ W_dt^T + b_dt)   [4096 x 2048], K=64
    gemm_abt<1><<<dim3(D_INNER / 128, M_ROWS / 128), 256>>>(
        xp, XP_COLS, W_dt, DT_RANK, dtp, D_INNER,
        M_ROWS, D_INNER, DT_RANK, b_dt);

    // 5) selective scan (fused D*x and silu(z) gate)
    {
        int warps = (B_SZ * D_INNER) / 2;     // 2048 warps
        int threads = warps * 32;             // 65536
        scan_kernel<<<threads / 256, 256>>>(dtp, x, xp, xz, A_log, D_par, y);
    }

    // 6) out = y @ W_out^T   [4096 x 1024], K=2048
    gemm_abt<0><<<dim3(D_MODEL / 128, M_ROWS / 128), 256>>>(
        y, D_INNER, W_out, D_INNER, out, D_MODEL,
        M_ROWS, D_MODEL, D_INNER, nullptr);
}

// round 2
// speedup vs baseline: 1.4491x; 1.4491x over previous
#include <cuda_runtime.h>
#include <cuda_bf16.h>
#include <cstdint>

// ---------------------------------------------------------------------------
// DualCausalMambaBlock: B=2, L=2048, D_MODEL=1024, D_INNER=2048, N=16,
// D_CONV=4, DT_RANK=64.  M = B*L = 4096 rows.
// GEMMs run on tensor cores: mma.sync m16n8k16 bf16, 2-term split precision
// (3 MMAs: hi*hi + lo*hi + hi*lo) for near-fp32 accuracy.
// ---------------------------------------------------------------------------

#define B_SZ     2
#define SEQ_L    2048
#define D_MODEL  1024
#define D_INNER  2048
#define D_STATE  16
#define D_CONV   4
#define DT_RANK  64
#define M_ROWS   (B_SZ * SEQ_L)          // 4096
#define XP_COLS  (DT_RANK + 2 * D_STATE) // 96

// Scratch (static device globals)
__device__ float g_xz[(size_t)M_ROWS * (2 * D_INNER)]; // 64 MB
__device__ float g_x [(size_t)M_ROWS * D_INNER];       // 32 MB
__device__ float g_xp[(size_t)M_ROWS * XP_COLS];       // 1.5 MB
__device__ float g_dt[(size_t)M_ROWS * D_INNER];       // 32 MB
__device__ float g_y [(size_t)M_ROWS * D_INNER];       // 32 MB

// ---------------------------------------------------------------------------
// helpers
// ---------------------------------------------------------------------------
__device__ __forceinline__ uint32_t f2bf2(float lo, float hi) {
    __nv_bfloat162 h = __floats2bfloat162_rn(lo, hi);
    return *reinterpret_cast<uint32_t*>(&h);
}

__device__ __forceinline__ void ldmx4(uint32_t* r, const void* p) {
    uint32_t a = (uint32_t)__cvta_generic_to_shared(p);
    asm volatile("ldmatrix.sync.aligned.m8n8.x4.shared.b16 {%0,%1,%2,%3}, [%4];"
                 : "=r"(r[0]), "=r"(r[1]), "=r"(r[2]), "=r"(r[3]) : "r"(a));
}

__device__ __forceinline__ void mma_bf16(float* c, const uint32_t* a, const uint32_t* b) {
    asm volatile(
        "mma.sync.aligned.m16n8k16.row.col.f32.bf16.bf16.f32 "
        "{%0,%1,%2,%3}, {%4,%5,%6,%7}, {%8,%9}, {%0,%1,%2,%3};"
        : "+f"(c[0]), "+f"(c[1]), "+f"(c[2]), "+f"(c[3])
        : "r"(a[0]), "r"(a[1]), "r"(a[2]), "r"(a[3]), "r"(b[0]), "r"(b[1]));
}

// ---------------------------------------------------------------------------
// Tensor-core GEMM:  C[M,N] = A[M,K] @ B[N,K]^T   (both K-major fp32)
// BM=128, BN=128, BK=32, 8 warps (2m x 4n), warp tile 64x32.
// Split-bf16 precision. ACT: 0 = none, 1 = softplus(v + bias[col]).
// Requirements: M % 128 == 0, K % 32 == 0, lda/ldb % 4 == 0, ldc even.
// ---------------------------------------------------------------------------
template<int ACT>
__global__ __launch_bounds__(256, 1)
void gemm_tc(const float* __restrict__ A, int lda,
             const float* __restrict__ B, int ldb,
             float* __restrict__ C, int ldc,
             int M, int N, int K,
             const float* __restrict__ bias)
{
    constexpr int BM = 128, BN = 128, BK = 32;
    // 4 tiles of [128 rows][32 bf16] = 64B rows, 8KB each
    __shared__ __align__(16) unsigned char smem_[4 * 128 * 64];
    unsigned char* smA_h = smem_;
    unsigned char* smA_l = smem_ + 1 * 8192;
    unsigned char* smB_h = smem_ + 2 * 8192;
    unsigned char* smB_l = smem_ + 3 * 8192;

    const int tid  = threadIdx.x;
    const int lane = tid & 31;
    const int warp = tid >> 5;
    const int wm   = warp >> 2;          // 0..1  (64 rows each)
    const int wn   = warp & 3;           // 0..3  (32 cols each)
    const int bm0  = blockIdx.y * BM;
    const int bn0  = blockIdx.x * BN;

    float acc[4][4][4];
#pragma unroll
    for (int i = 0; i < 4; ++i)
#pragma unroll
        for (int j = 0; j < 4; ++j)
#pragma unroll
            for (int k = 0; k < 4; ++k) acc[i][j][k] = 0.f;

    // loader: thread i handles float4 id = tid + i*256 (i=0..1 A, 0..1 B each
    // actually 4 float4 per matrix per stage: 1024 float4 per 128x32 tile)
    float4 rA[4], rB[4];

    auto load_tile = [&](int k0) {
#pragma unroll
        for (int i = 0; i < 4; ++i) {
            int id = tid + i * 256;
            int r  = id >> 3;
            int c4 = id & 7;
            // A rows always valid (M multiple of 128)
            rA[i] = *reinterpret_cast<const float4*>(A + (size_t)(bm0 + r) * lda + k0 + c4 * 4);
            int br = bn0 + r;
            if (br < N)
                rB[i] = *reinterpret_cast<const float4*>(B + (size_t)br * ldb + k0 + c4 * 4);
            else
                rB[i] = make_float4(0.f, 0.f, 0.f, 0.f);
        }
    };

    auto store_tile = [&]() {
#pragma unroll
        for (int i = 0; i < 4; ++i) {
            int id = tid + i * 256;
            int r  = id >> 3;
            int c4 = id & 7;
            int chunk = c4 >> 1;
            int sw = chunk ^ ((r >> 1) & 3);
            uint32_t off = r * 64 + (sw << 4) + (c4 & 1) * 8;

            float v[4] = { rA[i].x, rA[i].y, rA[i].z, rA[i].w };
            float h[4], l[4];
#pragma unroll
            for (int j = 0; j < 4; ++j) {
                __nv_bfloat16 hb = __float2bfloat16_rn(v[j]);
                h[j] = __bfloat162float(hb);
                l[j] = v[j] - h[j];
            }
            *reinterpret_cast<uint2*>(smA_h + off) = make_uint2(f2bf2(h[0], h[1]), f2bf2(h[2], h[3]));
            *reinterpret_cast<uint2*>(smA_l + off) = make_uint2(f2bf2(l[0], l[1]), f2bf2(l[2], l[3]));

            float w[4] = { rB[i].x, rB[i].y, rB[i].z, rB[i].w };
#pragma unroll
            for (int j = 0; j < 4; ++j) {
                __nv_bfloat16 hb = __float2bfloat16_rn(w[j]);
                h[j] = __bfloat162float(hb);
                l[j] = w[j] - h[j];
            }
            *reinterpret_cast<uint2*>(smB_h + off) = make_uint2(f2bf2(h[0], h[1]), f2bf2(h[2], h[3]));
            *reinterpret_cast<uint2*>(smB_l + off) = make_uint2(f2bf2(l[0], l[1]), f2bf2(l[2], l[3]));
        }
    };

    load_tile(0);

    for (int k0 = 0; k0 < K; k0 += BK) {
        __syncthreads();     // smem consumers of previous tile done
        store_tile();
        __syncthreads();

        if (k0 + BK < K) load_tile(k0 + BK);   // prefetch next tile into regs

#pragma unroll
        for (int kk = 0; kk < 2; ++kk) {       // two k16 steps per BK=32
            uint32_t ah[4][4], al[4][4], bh[4][2], bl[4][2];
#pragma unroll
            for (int tm = 0; tm < 4; ++tm) {
                int m = wm * 64 + tm * 16 + (lane & 15);
                int chunk = 2 * kk + (lane >> 4);
                uint32_t off = m * 64 + ((chunk ^ ((m >> 1) & 3)) << 4);
                ldmx4(ah[tm], smA_h + off);
                ldmx4(al[tm], smA_l + off);
            }
#pragma unroll
            for (int pn = 0; pn < 2; ++pn) {
                int n = wn * 32 + pn * 16 + (lane & 7) + ((lane >> 4) << 3);
                int chunk = 2 * kk + ((lane >> 3) & 1);
                uint32_t off = n * 64 + ((chunk ^ ((n >> 1) & 3)) << 4);
                uint32_t r[4];
                ldmx4(r, smB_h + off);
                bh[2 * pn][0] = r[0]; bh[2 * pn][1] = r[1];
                bh[2 * pn + 1][0] = r[2]; bh[2 * pn + 1][1] = r[3];
                ldmx4(r, smB_l + off);
                bl[2 * pn][0] = r[0]; bl[2 * pn][1] = r[1];
                bl[2 * pn + 1][0] = r[2]; bl[2 * pn + 1][1] = r[3];
            }
#pragma unroll
            for (int tm = 0; tm < 4; ++tm)
#pragma unroll
                for (int tn = 0; tn < 4; ++tn) {
                    mma_bf16(acc[tm][tn], ah[tm], bh[tn]);
                    mma_bf16(acc[tm][tn], al[tm], bh[tn]);
                    mma_bf16(acc[tm][tn], ah[tm], bl[tn]);
                }
        }
    }

    // epilogue
    const int g = lane >> 2, t = lane & 3;
#pragma unroll
    for (int tm = 0; tm < 4; ++tm) {
        int row0 = bm0 + wm * 64 + tm * 16 + g;
#pragma unroll
        for (int tn = 0; tn < 4; ++tn) {
            int col = bn0 + wn * 32 + tn * 8 + 2 * t;
            if (col >= N) continue;
            float v0 = acc[tm][tn][0], v1 = acc[tm][tn][1];
            float v2 = acc[tm][tn][2], v3 = acc[tm][tn][3];
            if (ACT == 1) {
                float b0 = bias[col], b1 = bias[col + 1];
                v0 += b0; v1 += b1; v2 += b0; v3 += b1;
                v0 = (v0 > 20.f) ? v0 : log1pf(__expf(v0));
                v1 = (v1 > 20.f) ? v1 : log1pf(__expf(v1));
                v2 = (v2 > 20.f) ? v2 : log1pf(__expf(v2));
                v3 = (v3 > 20.f) ? v3 : log1pf(__expf(v3));
            }
            *reinterpret_cast<float2*>(C + (size_t)row0 * ldc + col)       = make_float2(v0, v1);
            *reinterpret_cast<float2*>(C + (size_t)(row0 + 8) * ldc + col) = make_float2(v2, v3);
        }
    }
}

// ---------------------------------------------------------------------------
// Causal depthwise conv (K=4) + SiLU.
// ---------------------------------------------------------------------------
__global__ __launch_bounds__(256)
void conv_silu_kernel(const float* __restrict__ xz,
                      const float* __restrict__ cw,
                      const float* __restrict__ cb,
                      float* __restrict__ x)
{
    int idx = blockIdx.x * blockDim.x + threadIdx.x;
    if (idx >= B_SZ * SEQ_L * D_INNER) return;
    int d = idx & (D_INNER - 1);
    int l = (idx >> 11) & (SEQ_L - 1);
    int b = idx >> 22;

    float acc = cb[d];
#pragma unroll
    for (int k = 0; k < D_CONV; ++k) {
        int ls = l - (D_CONV - 1) + k;
        if (ls >= 0)
            acc = fmaf(xz[((size_t)(b * SEQ_L + ls)) * (2 * D_INNER) + d],
                       cw[d * D_CONV + k], acc);
    }
    float s = 1.f / (1.f + __expf(-acc));
    x[idx] = acc * s;
}

// ---------------------------------------------------------------------------
// Selective scan. Half-warp per channel, lane n holds state h[n].
// Fused with y = (scan + D*x) * silu(z).
// ---------------------------------------------------------------------------
__global__ __launch_bounds__(256)
void scan_kernel(const float* __restrict__ dt,
                 const float* __restrict__ xv,
                 const float* __restrict__ xp,
                 const float* __restrict__ xz,
                 const float* __restrict__ A_log,
                 const float* __restrict__ Dp,
                 float* __restrict__ y)
{
    int gw   = (blockIdx.x * blockDim.x + threadIdx.x) >> 5;
    int lane = threadIdx.x & 31;
    int sub  = lane >> 4;
    int n    = lane & 15;

    int ch = gw * 2 + sub;
    if (ch >= B_SZ * D_INNER) return;
    int b = ch / D_INNER;
    int d = ch % D_INNER;

    const float Aval = -__expf(A_log[d * D_STATE + n]);
    const float Dv   = Dp[d];

    float h = 0.f;
    const int base_row = b * SEQ_L;

    for (int t = 0; t < SEQ_L; ++t) {
        int row = base_row + t;
        float dtv = dt[(size_t)row * D_INNER + d];
        float xt  = xv[(size_t)row * D_INNER + d];
        float zt  = xz[(size_t)row * (2 * D_INNER) + D_INNER + d];
        const float* xpr = xp + (size_t)row * XP_COLS;
        float Bv = xpr[DT_RANK + n];
        float Cv = xpr[DT_RANK + D_STATE + n];

        float a = __expf(dtv * Aval);
        h = fmaf(a, h, (dtv * xt) * Bv);

        float p = h * Cv;
        p += __shfl_xor_sync(0xffffffffu, p, 8);
        p += __shfl_xor_sync(0xffffffffu, p, 4);
        p += __shfl_xor_sync(0xffffffffu, p, 2);
        p += __shfl_xor_sync(0xffffffffu, p, 1);

        if (n == 0) {
            float yv = fmaf(Dv, xt, p);
            float sz = zt / (1.f + __expf(-zt));
            y[(size_t)row * D_INNER + d] = yv * sz;
        }
    }
}

// ---------------------------------------------------------------------------
extern "C" void kernel_launch(void* const* d_in, const int* in_sizes, int n_in,
                              void* d_out, int out_size)
{
    const float* u      = (const float*)d_in[0];
    const float* W_in   = (const float*)d_in[1];
    const float* W_out  = (const float*)d_in[2];
    const float* conv_w = (const float*)d_in[3];
    const float* conv_b = (const float*)d_in[4];
    const float* W_x    = (const float*)d_in[5];
    const float* W_dt   = (const float*)d_in[6];
    const float* b_dt   = (const float*)d_in[7];
    const float* A_log  = (const float*)d_in[8];
    const float* D_par  = (const float*)d_in[9];
    float* out = (float*)d_out;

    float *xz, *x, *xp, *dtp, *y;
    cudaGetSymbolAddress((void**)&xz,  g_xz);
    cudaGetSymbolAddress((void**)&x,   g_x);
    cudaGetSymbolAddress((void**)&xp,  g_xp);
    cudaGetSymbolAddress((void**)&dtp, g_dt);
    cudaGetSymbolAddress((void**)&y,   g_y);

    // 1) xz = u @ W_in^T   [4096 x 4096], K=1024
    gemm_tc<0><<<dim3((2 * D_INNER) / 128, M_ROWS / 128), 256>>>(
        u, D_MODEL, W_in, D_MODEL, xz, 2 * D_INNER,
        M_ROWS, 2 * D_INNER, D_MODEL, nullptr);

    // 2) causal conv + silu
    {
        int total = B_SZ * SEQ_L * D_INNER;
        conv_silu_kernel<<<(total + 255) / 256, 256>>>(xz, conv_w, conv_b, x);
    }

    // 3) xp = x @ W_x^T   [4096 x 96], K=2048
    gemm_tc<0><<<dim3(1, M_ROWS / 128), 256>>>(
        x, D_INNER, W_x, D_INNER, xp, XP_COLS,
        M_ROWS, XP_COLS, D_INNER, nullptr);

    // 4) dt = softplus(xp[:, :64] @ W_dt^T + b_dt)   [4096 x 2048], K=64
    gemm_tc<1><<<dim3(D_INNER / 128, M_ROWS / 128), 256>>>(
        xp, XP_COLS, W_dt, DT_RANK, dtp, D_INNER,
        M_ROWS, D_INNER, DT_RANK, b_dt);

    // 5) selective scan
    {
        int warps = (B_SZ * D_INNER) / 2;
        int threads = warps * 32;
        scan_kernel<<<threads / 256, 256>>>(dtp, x, xp, xz, A_log, D_par, y);
    }

    // 6) out = y @ W_out^T   [4096 x 1024], K=2048
    gemm_tc<0><<<dim3(D_MODEL / 128, M_ROWS / 128), 256>>>(
        y, D_INNER, W_out, D_INNER, out, D_MODEL,
        M_ROWS, D_MODEL, D_INNER, nullptr);
}